// round 5
// baseline (speedup 1.0000x reference)
#include <cuda_runtime.h>

// LocalPosEnc2D: bilinear grid sample (513x513 x 24ch) + sinusoidal PE gating.
//   coords: (B,2) float32   grids: (513*513, 24) float32   out: (B,24) float32
// (Harness canonicalizes jnp.float16 to float32 — its type table is
//  {float32, int32, bfloat16}, and bf16 was disproven empirically in R4.)

#define GRID_ELEMS (513 * 513 * 24)
#define TWO_PI_F 6.28318530717958647692f

__global__ __launch_bounds__(256) void lpe2d_kernel(
    const float2* __restrict__ coords,
    const float4* __restrict__ grids,   // each grid row = 6 float4 (24 floats)
    float4*       __restrict__ out,     // each out row  = 6 float4 (24 floats)
    int B)
{
    int b = blockIdx.x * blockDim.x + threadIdx.x;
    if (b >= B) return;

    float2 c = coords[b];
    float u = fminf(fmaxf(c.x, 0.0f), 1.0f - 1e-6f);
    float v = fminf(fmaxf(c.y, 0.0f), 1.0f - 1e-6f);
    float fu = u * 512.0f;
    float fv = v * 512.0f;
    int iu = (int)fu; iu = iu > 511 ? 511 : iu;
    int iv = (int)fv; iv = iv > 511 ? 511 : iv;
    float lu = fu - (float)iu;
    float lv = fv - (float)iv;

    int idx00 = iu + iv * 513;
    const float4* r0 = grids + (size_t)idx00 * 6;          // rows idx00, idx00+1 (192B contig)
    const float4* r1 = grids + (size_t)(idx00 + 513) * 6;  // rows idx01, idx01+1

    // Issue all 24 gathers up front (independent -> high MLP).
    float4 q00[6], q10[6], q01[6], q11[6];
#pragma unroll
    for (int j = 0; j < 6; j++) {
        q00[j] = r0[j];
        q10[j] = r0[j + 6];
        q01[j] = r1[j];
        q11[j] = r1[j + 6];
    }

    // pe[0..3]=cos(2^k*2pi*lu), pe[4..7]=sin(2^k*2pi*lu),
    // pe[8..11]=cos(2^k*2pi*lv), pe[12..15]=sin(2^k*2pi*lv).
    float pe[16];
    {
        float t = lu;
#pragma unroll
        for (int k = 0; k < 4; k++) {
            float r = t - floorf(t);
            float s, cc;
            sincosf(r * TWO_PI_F, &s, &cc);
            pe[k]     = cc;
            pe[4 + k] = s;
            t *= 2.0f;
        }
        t = lv;
#pragma unroll
        for (int k = 0; k < 4; k++) {
            float r = t - floorf(t);
            float s, cc;
            sincosf(r * TWO_PI_F, &s, &cc);
            pe[8 + k]  = cc;
            pe[12 + k] = s;
            t *= 2.0f;
        }
    }

    float4* ob = out + (size_t)b * 6;
#pragma unroll
    for (int j = 0; j < 6; j++) {
        const float* a  = (const float*)&q00[j];
        const float* bb = (const float*)&q10[j];
        const float* cc = (const float*)&q01[j];
        const float* dd = (const float*)&q11[j];
        float4 o;
        float* op = (float*)&o;
#pragma unroll
        for (int w = 0; w < 4; w++) {
            float top = fmaf(lu, bb[w] - a[w], a[w]);
            float bot = fmaf(lu, dd[w] - cc[w], cc[w]);
            float res = fmaf(lv, bot - top, top);
            int ch = j * 4 + w;
            if (ch >= 8) res *= pe[ch - 8];
            op[w] = res;
        }
        ob[j] = o;
    }
}

extern "C" void kernel_launch(void* const* d_in, const int* in_sizes, int n_in,
                              void* d_out, int out_size) {
    // Detect input binding by size: grids has exactly 513*513*24 elements.
    int gi = -1, ci = -1;
    for (int i = 0; i < n_in; i++) {
        if (in_sizes[i] == GRID_ELEMS && gi < 0) gi = i;
    }
    for (int i = 0; i < n_in; i++) {
        if (i != gi && ci < 0) ci = i;
    }
    if (gi < 0) { gi = 1; ci = 0; }  // fallback: assume (coords, grids)

    const float2* coords = (const float2*)d_in[ci];
    const float4* grids  = (const float4*)d_in[gi];
    float4*       out    = (float4*)d_out;
    int B = out_size / 24;          // out is (B, 24) fp32
    int threads = 256;
    int blocks = (B + threads - 1) / threads;
    lpe2d_kernel<<<blocks, threads>>>(coords, grids, out, B);
}

// round 6
// speedup vs baseline: 1.4945x; 1.4945x over previous
#include <cuda_runtime.h>
#include <cuda_fp16.h>

// LocalPosEnc2D: bilinear grid sample (513x513 x 24ch, fp32) + sinusoidal PE gating.
//   coords: (B,2) fp32   grids: (513*513, 24) fp32   out: (B,24) fp32
// Cooperative layout: 6 lanes per point, lane j owns channels 4j..4j+3
// (one float4 chunk per corner row). Corner rows (idx,idx+1) are contiguous
// 192B segments -> coalesced within each 6-lane group.

#define GRID_ELEMS (513 * 513 * 24)
#define TWO_PI_F 6.28318530717958647692f

__global__ __launch_bounds__(192) void lpe2d_kernel(
    const float2* __restrict__ coords,
    const float4* __restrict__ grids,   // grid row = 6 float4 (24 floats)
    float4*       __restrict__ out,     // out row  = 6 float4 (24 floats)
    int B)
{
    int gtid = blockIdx.x * blockDim.x + threadIdx.x;   // <= 12.6M, fits int
    int p = gtid / 6;          // point index
    int j = gtid - p * 6;      // chunk role 0..5 (channels 4j..4j+3)
    if (p >= B) return;

    float2 c = coords[p];      // 6 lanes same address -> broadcast
    float u = fminf(fmaxf(c.x, 0.0f), 1.0f - 1e-6f);
    float v = fminf(fmaxf(c.y, 0.0f), 1.0f - 1e-6f);
    float fu = u * 512.0f;
    float fv = v * 512.0f;
    int iu = (int)fu; iu = iu > 511 ? 511 : iu;
    int iv = (int)fv; iv = iv > 511 ? 511 : iv;
    float lu = fu - (float)iu;
    float lv = fv - (float)iv;

    int idx00 = iu + iv * 513;
    const float4* r0 = grids + (size_t)idx00 * 6;          // rows idx00, idx00+1 (192B)
    const float4* r1 = grids + (size_t)(idx00 + 513) * 6;  // rows idx01, idx01+1 (192B)

    // 4 independent 16B gathers; consecutive lanes in each 6-lane group hit
    // consecutive addresses -> few L1 wavefronts, exact 32B-sector use.
    float4 a  = r0[j];
    float4 bq = r0[j + 6];
    float4 cq = r1[j];
    float4 dq = r1[j + 6];

    // Gate PE for this lane's channels (lanes 0,1 = base channels: gate = 1).
    float pe0 = 1.0f, pe1 = 1.0f, pe2 = 1.0f, pe3 = 1.0f;
    if (j >= 2) {
        int g = j - 2;                       // 0:cos(lu) 1:sin(lu) 2:cos(lv) 3:sin(lv)
        float l = (g < 2) ? lu : lv;
        float s0, c0, s1, c1, s2, c2, s3, c3;
        sincosf(l * (TWO_PI_F * 1.0f), &s0, &c0);
        sincosf(l * (TWO_PI_F * 2.0f), &s1, &c1);
        sincosf(l * (TWO_PI_F * 4.0f), &s2, &c2);
        sincosf(l * (TWO_PI_F * 8.0f), &s3, &c3);
        bool use_sin = (g & 1);
        pe0 = use_sin ? s0 : c0;
        pe1 = use_sin ? s1 : c1;
        pe2 = use_sin ? s2 : c2;
        pe3 = use_sin ? s3 : c3;
    }

    float wu0 = 1.0f - lu, wv0 = 1.0f - lv;
    const float* ap = (const float*)&a;
    const float* bp = (const float*)&bq;
    const float* cp = (const float*)&cq;
    const float* dp = (const float*)&dq;
    float pes[4] = {pe0, pe1, pe2, pe3};

    float4 o;
    float* op = (float*)&o;
#pragma unroll
    for (int w = 0; w < 4; w++) {
        float top = ap[w] * wu0 + bp[w] * lu;    // mirror reference expression
        float bot = cp[w] * wu0 + dp[w] * lu;
        float res = top * wv0 + bot * lv;
        res *= pes[w];
        // Reference casts its fp32 result to float16; harness promotes both
        // sides back to fp32. Match that final rounding exactly.
        op[w] = __half2float(__float2half_rn(res));
    }

    out[(size_t)p * 6 + j] = o;                  // fully coalesced 96B/point
}

extern "C" void kernel_launch(void* const* d_in, const int* in_sizes, int n_in,
                              void* d_out, int out_size) {
    // Bind inputs by size: grids has exactly 513*513*24 elements.
    int gi = -1, ci = -1;
    for (int i = 0; i < n_in; i++)
        if (in_sizes[i] == GRID_ELEMS && gi < 0) gi = i;
    for (int i = 0; i < n_in; i++)
        if (i != gi && ci < 0) ci = i;
    if (gi < 0) { gi = 1; ci = 0; }

    const float2* coords = (const float2*)d_in[ci];
    const float4* grids  = (const float4*)d_in[gi];
    float4*       out    = (float4*)d_out;
    int B = out_size / 24;                       // out is (B, 24) fp32
    long long threads_total = (long long)B * 6;
    int threads = 192;
    int blocks = (int)((threads_total + threads - 1) / threads);
    lpe2d_kernel<<<blocks, threads>>>(coords, grids, out, B);
}